// round 2
// baseline (speedup 1.0000x reference)
#include <cuda_runtime.h>
#include <math.h>

#define BATCH 8
#define CIN   64
#define COUT  128
#define EDIM  128
#define HIN   192
#define WIN   384
#define OH    96
#define OW    192
#define TOPK  32
#define OUT6_SIZE (BATCH*COUT*OH*OW)

typedef unsigned long long u64;

// ---- scratch (no cudaMalloc allowed) ----
__device__ float d_out2[BATCH*TOPK*OH*OW];   // leaky(conv1*g1), compact channels
__device__ float d_out4[BATCH*TOPK*OH*OW];   // leaky(conv2*g2), compact channels
__device__ int   d_idx1[BATCH*TOPK];
__device__ float d_gv1 [BATCH*TOPK];
__device__ int   d_idx2[BATCH*TOPK];
__device__ float d_gv2 [BATCH*TOPK];
__device__ int   d_slot2[BATCH*COUT];        // channel -> compact slot in d_out4, or -1

__device__ __forceinline__ float leaky(float v) { return v >= 0.f ? v : 0.2f * v; }

__device__ __forceinline__ u64 pk2(float lo, float hi) {
    u64 r; asm("mov.b64 %0, {%1, %2};" : "=l"(r) : "f"(lo), "f"(hi)); return r;
}
__device__ __forceinline__ void upk2(u64 v, float& lo, float& hi) {
    asm("mov.b64 {%0, %1}, %2;" : "=f"(lo), "=f"(hi) : "l"(v));
}
__device__ __forceinline__ void fma2(u64& d, u64 a, u64 b) {
    asm("fma.rn.f32x2 %0, %1, %2, %0;" : "+l"(d) : "l"(a), "l"(b));
}

// ============================================================================
// Gate kernel: logits = emb @ W + b ; top-32 (tie-break lower index) ; softmax
// ============================================================================
__global__ void gate_kernel(const float* __restrict__ emb,
                            const float* __restrict__ g1w, const float* __restrict__ g1b,
                            const float* __restrict__ g2w, const float* __restrict__ g2b,
                            float* __restrict__ out) {
    const int b    = blockIdx.x;
    const int gate = blockIdx.y;
    const int c    = threadIdx.x;
    const float* gw = (gate == 0) ? g1w : g2w;
    const float* gb = (gate == 0) ? g1b : g2b;

    __shared__ float s_emb[EDIM];
    __shared__ float s_log[COUT];
    __shared__ float s_exp[COUT];

    s_emb[c] = emb[b * EDIM + c];
    __syncthreads();

    float l = gb[c];
    #pragma unroll 8
    for (int e = 0; e < EDIM; e++) l += s_emb[e] * gw[e * COUT + c];
    s_log[c] = l;
    __syncthreads();

    int rank = 0;
    float m = -1e30f;
    for (int j = 0; j < COUT; j++) {
        float lj = s_log[j];
        if (lj > l || (lj == l && j < c)) rank++;
        if (lj > m) m = lj;
    }
    bool sel = (rank < TOPK);
    float ev = sel ? expf(l - m) : 0.0f;
    s_exp[c] = ev;
    __syncthreads();

    float s = 0.f;
    for (int j = 0; j < COUT; j++) s += s_exp[j];
    float gv = ev / s;

    out[OUT6_SIZE + gate * (BATCH * COUT) + b * COUT + c] = gv;

    if (gate == 0) {
        if (sel) { d_idx1[b * TOPK + rank] = c; d_gv1[b * TOPK + rank] = gv; }
    } else {
        d_slot2[b * COUT + c] = sel ? rank : -1;
        if (sel) { d_idx2[b * TOPK + rank] = c; d_gv2[b * TOPK + rank] = gv; }
    }
}

// ============================================================================
// conv1: 3x3 stride 2 pad 1, 32 gated output channels, packed f32x2 math.
// Tile: 8 rows x 64 cols of output. Each thread: 2 adjacent output pixels.
// grid (36, BATCH): 12 h-tiles x 3 w-tiles. block 256 (py=tid>>5, px=tid&31).
// Weights duplicated in smem: per (ci,co) 20 floats (w0,w0,w1,w1,...,w8,w8,p,p).
// ============================================================================
#define C1_XSTR 132            // padded row stride of patch (129 used)
__global__ void __launch_bounds__(256) conv1_kernel(const float* __restrict__ x,
                                                    const float* __restrict__ w1) {
    const int b    = blockIdx.y;
    const int tile = blockIdx.x;
    const int h0 = (tile / 3) * 8;
    const int w0 = (tile % 3) * 64;
    const int tid = threadIdx.x;
    const int py = tid >> 5, px = tid & 31;

    __shared__ int   s_idx[TOPK];
    __shared__ float s_gv[TOPK];
    __shared__ __align__(16) float s_w[8 * TOPK * 20];     // 20.5 KB
    __shared__ __align__(16) float s_x[2][17 * C1_XSTR];   // 17.9 KB

    if (tid < TOPK) { s_idx[tid] = d_idx1[b * TOPK + tid]; s_gv[tid] = d_gv1[b * TOPK + tid]; }

    u64 acc[TOPK];
    #pragma unroll
    for (int i = 0; i < TOPK; i++) acc[i] = 0ull;

    for (int chunk = 0; chunk < 8; chunk++) {          // 8 chunks of 8 input channels
        __syncthreads();                               // prev chunk done with s_w (and s_idx init)
        for (int i = tid; i < 8 * TOPK * 9; i += 256) {
            int ci_l = i / (TOPK * 9);
            int r = i % (TOPK * 9);
            int co = r / 9, k = r % 9;
            float wv = w1[(s_idx[co] * CIN + (chunk * 8 + ci_l)) * 9 + k];
            float* dst = &s_w[(ci_l * TOPK + co) * 20 + 2 * k];
            dst[0] = wv; dst[1] = wv;
        }
        for (int step = 0; step < 4; step++) {         // 2 ci per staging step
            __syncthreads();                           // prev step done with s_x; s_w gathered
            for (int i = tid; i < 2 * 17 * 129; i += 256) {
                int buf = i / (17 * 129);
                int j = i % (17 * 129);
                int r = j / 129, cl = j % 129;
                int gr = 2 * h0 - 1 + r, gc = 2 * w0 - 1 + cl;
                int ci = chunk * 8 + step * 2 + buf;
                float v = 0.f;
                if (gr >= 0 && gr < HIN && gc >= 0 && gc < WIN)
                    v = x[((b * CIN + ci) * HIN + gr) * WIN + gc];
                s_x[buf][r * C1_XSTR + cl] = v;
            }
            __syncthreads();
            #pragma unroll
            for (int buf = 0; buf < 2; buf++) {
                const int ci_l = step * 2 + buf;
                const float* xp = &s_x[buf][(2 * py) * C1_XSTR + 4 * px];
                u64 p[9];
                #pragma unroll
                for (int r = 0; r < 3; r++) {
                    float4 a = *(const float4*)(xp + r * C1_XSTR);
                    float  e = xp[r * C1_XSTR + 4];
                    p[r * 3 + 0] = pk2(a.x, a.z);
                    p[r * 3 + 1] = pk2(a.y, a.w);
                    p[r * 3 + 2] = pk2(a.z, e);
                }
                const float* wc = &s_w[ci_l * TOPK * 20];
                #pragma unroll
                for (int co = 0; co < TOPK; co++) {
                    const u64* wp = (const u64*)(wc + co * 20);
                    ulonglong2 q0 = *(const ulonglong2*)(wp + 0);
                    ulonglong2 q1 = *(const ulonglong2*)(wp + 2);
                    ulonglong2 q2 = *(const ulonglong2*)(wp + 4);
                    ulonglong2 q3 = *(const ulonglong2*)(wp + 6);
                    u64        q4 = wp[8];
                    fma2(acc[co], p[0], q0.x); fma2(acc[co], p[1], q0.y);
                    fma2(acc[co], p[2], q1.x); fma2(acc[co], p[3], q1.y);
                    fma2(acc[co], p[4], q2.x); fma2(acc[co], p[5], q2.y);
                    fma2(acc[co], p[6], q3.x); fma2(acc[co], p[7], q3.y);
                    fma2(acc[co], p[8], q4);
                }
            }
        }
    }

    const int h = h0 + py, w = w0 + 2 * px;
    #pragma unroll
    for (int co = 0; co < TOPK; co++) {
        float lo, hi; upk2(acc[co], lo, hi);
        float g = s_gv[co];
        float2 o;
        o.x = leaky(lo * g);
        o.y = leaky(hi * g);
        *(float2*)&d_out2[((b * TOPK + co) * OH + h) * OW + w] = o;
    }
}

// ============================================================================
// conv2: 3x3 stride 1 pad 1, 32 compact in -> 32 compact out, packed f32x2.
// Same 8x64 output tile. grid (36, BATCH), block 256.
// ============================================================================
#define C2_XSTR 68
__global__ void __launch_bounds__(256) conv2_kernel(const float* __restrict__ w2) {
    const int b    = blockIdx.y;
    const int tile = blockIdx.x;
    const int h0 = (tile / 3) * 8;
    const int w0 = (tile % 3) * 64;
    const int tid = threadIdx.x;
    const int py = tid >> 5, px = tid & 31;

    __shared__ int   s_idx1[TOPK];
    __shared__ int   s_idx2[TOPK];
    __shared__ float s_gv[TOPK];
    __shared__ __align__(16) float s_w[8 * TOPK * 20];    // 20.5 KB
    __shared__ __align__(16) float s_x[4][10 * C2_XSTR];  // 10.9 KB

    if (tid < TOPK) {
        s_idx1[tid] = d_idx1[b * TOPK + tid];
        s_idx2[tid] = d_idx2[b * TOPK + tid];
        s_gv[tid]   = d_gv2[b * TOPK + tid];
    }

    u64 acc[TOPK];
    #pragma unroll
    for (int i = 0; i < TOPK; i++) acc[i] = 0ull;

    for (int chunk = 0; chunk < 4; chunk++) {          // 4 chunks of 8 input slots
        __syncthreads();
        for (int i = tid; i < 8 * TOPK * 9; i += 256) {
            int ci_l = i / (TOPK * 9);
            int r = i % (TOPK * 9);
            int co = r / 9, k = r % 9;
            float wv = w2[(s_idx2[co] * COUT + s_idx1[chunk * 8 + ci_l]) * 9 + k];
            float* dst = &s_w[(ci_l * TOPK + co) * 20 + 2 * k];
            dst[0] = wv; dst[1] = wv;
        }
        for (int step = 0; step < 2; step++) {         // 4 ci per staging step
            __syncthreads();
            for (int i = tid; i < 4 * 10 * 66; i += 256) {
                int buf = i / (10 * 66);
                int j = i % (10 * 66);
                int r = j / 66, cl = j % 66;
                int gr = h0 - 1 + r, gc = w0 - 1 + cl;
                int ci = chunk * 8 + step * 4 + buf;
                float v = 0.f;
                if (gr >= 0 && gr < OH && gc >= 0 && gc < OW)
                    v = d_out2[((b * TOPK + ci) * OH + gr) * OW + gc];
                s_x[buf][r * C2_XSTR + cl] = v;
            }
            __syncthreads();
            #pragma unroll
            for (int buf = 0; buf < 4; buf++) {
                const int ci_l = step * 4 + buf;
                const float* xp = &s_x[buf][py * C2_XSTR + 2 * px];
                u64 p[9];
                #pragma unroll
                for (int r = 0; r < 3; r++) {
                    float2 a = *(const float2*)(xp + r * C2_XSTR);
                    float2 c = *(const float2*)(xp + r * C2_XSTR + 2);
                    p[r * 3 + 0] = pk2(a.x, a.y);
                    p[r * 3 + 1] = pk2(a.y, c.x);
                    p[r * 3 + 2] = pk2(c.x, c.y);
                }
                const float* wc = &s_w[ci_l * TOPK * 20];
                #pragma unroll
                for (int co = 0; co < TOPK; co++) {
                    const u64* wp = (const u64*)(wc + co * 20);
                    ulonglong2 q0 = *(const ulonglong2*)(wp + 0);
                    ulonglong2 q1 = *(const ulonglong2*)(wp + 2);
                    ulonglong2 q2 = *(const ulonglong2*)(wp + 4);
                    ulonglong2 q3 = *(const ulonglong2*)(wp + 6);
                    u64        q4 = wp[8];
                    fma2(acc[co], p[0], q0.x); fma2(acc[co], p[1], q0.y);
                    fma2(acc[co], p[2], q1.x); fma2(acc[co], p[3], q1.y);
                    fma2(acc[co], p[4], q2.x); fma2(acc[co], p[5], q2.y);
                    fma2(acc[co], p[6], q3.x); fma2(acc[co], p[7], q3.y);
                    fma2(acc[co], p[8], q4);
                }
            }
        }
    }

    const int h = h0 + py, w = w0 + 2 * px;
    #pragma unroll
    for (int co = 0; co < TOPK; co++) {
        float lo, hi; upk2(acc[co], lo, hi);
        float g = s_gv[co];
        float2 o;
        o.x = leaky(lo * g);
        o.y = leaky(hi * g);
        *(float2*)&d_out4[((b * TOPK + co) * OH + h) * OW + w] = o;
    }
}

// ============================================================================
// ds: dense 1x1 stride-2 conv + BN(eval) + add sparse out4 + leaky -> out6.
// grid (36, 4, BATCH): 8x64-pixel tiles x 4 groups of 32 channels.
// Packed f32x2: thread owns 2 adjacent output pixels; one LDG.128 per ci.
// ============================================================================
__global__ void __launch_bounds__(256) ds_kernel(const float* __restrict__ x,
                                                 const float* __restrict__ dsw,
                                                 const float* __restrict__ gamma,
                                                 const float* __restrict__ beta,
                                                 float* __restrict__ out) {
    const int b    = blockIdx.z;
    const int cg   = blockIdx.y;
    const int tile = blockIdx.x;
    const int h0 = (tile / 3) * 8;
    const int w0 = (tile % 3) * 64;
    const int tid = threadIdx.x;
    const int py = tid >> 5, px = tid & 31;
    const int h = h0 + py, w = w0 + 2 * px;

    __shared__ __align__(16) float s_w[CIN * 2 * TOPK];   // dup pairs: 16 KB
    __shared__ float s_scale[TOPK];
    __shared__ float s_beta[TOPK];
    __shared__ int   s_slot[TOPK];

    for (int i = tid; i < CIN * TOPK; i += 256) {
        int ci = i / TOPK, co = i % TOPK;
        float wv = dsw[(cg * TOPK + co) * CIN + ci];
        float* dst = &s_w[ci * 2 * TOPK + 2 * co];
        dst[0] = wv; dst[1] = wv;
    }
    if (tid < TOPK) {
        int c = cg * TOPK + tid;
        s_scale[tid] = gamma[c] * rsqrtf(1.0f + 1e-5f);
        s_beta[tid]  = beta[c];
        s_slot[tid]  = d_slot2[b * COUT + c];
    }
    __syncthreads();

    u64 acc[TOPK];
    #pragma unroll
    for (int i = 0; i < TOPK; i++) acc[i] = 0ull;

    const float* xb = x + ((size_t)b * CIN * HIN + 2 * h) * WIN + 2 * w;
    #pragma unroll 4
    for (int ci = 0; ci < CIN; ci++) {
        float4 xv = *(const float4*)(xb + (size_t)ci * HIN * WIN);
        u64 xp = pk2(xv.x, xv.z);
        const u64* wr = (const u64*)&s_w[ci * 2 * TOPK];
        #pragma unroll
        for (int co = 0; co < TOPK; co += 2) {
            ulonglong2 q = *(const ulonglong2*)(wr + co);
            fma2(acc[co],     xp, q.x);
            fma2(acc[co + 1], xp, q.y);
        }
    }

    #pragma unroll
    for (int co = 0; co < TOPK; co++) {
        int c = cg * TOPK + co;
        float lo, hi; upk2(acc[co], lo, hi);
        float sc = s_scale[co], be = s_beta[co];
        lo = lo * sc + be;
        hi = hi * sc + be;
        int slot = s_slot[co];
        if (slot >= 0) {
            float2 a = *(const float2*)&d_out4[((b * TOPK + slot) * OH + h) * OW + w];
            lo += a.x; hi += a.y;
        }
        float2 o;
        o.x = leaky(lo);
        o.y = leaky(hi);
        *(float2*)&out[((b * COUT + c) * OH + h) * OW + w] = o;
    }
}

// ============================================================================
extern "C" void kernel_launch(void* const* d_in, const int* in_sizes, int n_in,
                              void* d_out, int out_size) {
    const float* x     = (const float*)d_in[0];
    const float* emb   = (const float*)d_in[1];
    const float* w1    = (const float*)d_in[2];
    const float* w2    = (const float*)d_in[3];
    const float* dsw   = (const float*)d_in[4];
    const float* gam   = (const float*)d_in[5];
    const float* bet   = (const float*)d_in[6];
    const float* g1w   = (const float*)d_in[7];
    const float* g1b   = (const float*)d_in[8];
    const float* g2w   = (const float*)d_in[9];
    const float* g2b   = (const float*)d_in[10];
    float* out = (float*)d_out;

    gate_kernel<<<dim3(BATCH, 2), 128>>>(emb, g1w, g1b, g2w, g2b, out);
    conv1_kernel<<<dim3(36, BATCH), 256>>>(x, w1);
    conv2_kernel<<<dim3(36, BATCH), 256>>>(w2);
    ds_kernel<<<dim3(36, 4, BATCH), 256>>>(x, dsw, gam, bet, out);
}

// round 3
// speedup vs baseline: 1.1171x; 1.1171x over previous
#include <cuda_runtime.h>
#include <math.h>

#define BATCH 8
#define CIN   64
#define COUT  128
#define EDIM  128
#define HIN   192
#define WIN   384
#define OH    96
#define OW    192
#define TOPK  32
#define OUT6_SIZE (BATCH*COUT*OH*OW)

// padded conv2 input: rows 98 (1+96+1), col stride 196 (2+192+1+1)
#define P2H 98
#define P2W 196

typedef unsigned long long u64;

// ---- scratch (zero-initialized at module load; borders never written) ----
__device__ float d_out2p[BATCH*TOPK*P2H*P2W];  // padded leaky(conv1*g1)
__device__ float d_out4[BATCH*TOPK*OH*OW];     // leaky(conv2*g2), compact
__device__ int   d_idx1[BATCH*TOPK];
__device__ float d_gv1 [BATCH*TOPK];
__device__ int   d_idx2[BATCH*TOPK];
__device__ float d_gv2 [BATCH*TOPK];
__device__ int   d_slot2[BATCH*COUT];

__device__ __forceinline__ float leaky(float v) { return v >= 0.f ? v : 0.2f * v; }

__device__ __forceinline__ u64 pk2(float lo, float hi) {
    u64 r; asm("mov.b64 %0, {%1, %2};" : "=l"(r) : "f"(lo), "f"(hi)); return r;
}
__device__ __forceinline__ void upk2(u64 v, float& lo, float& hi) {
    asm("mov.b64 {%0, %1}, %2;" : "=f"(lo), "=f"(hi) : "l"(v));
}
__device__ __forceinline__ void fma2(u64& d, u64 a, u64 b) {
    asm("fma.rn.f32x2 %0, %1, %2, %0;" : "+l"(d) : "l"(a), "l"(b));
}
__device__ __forceinline__ unsigned smem_u32(const void* p) {
    return (unsigned)__cvta_generic_to_shared(p);
}
__device__ __forceinline__ void cp4(unsigned dst, const void* src, int sz) {
    asm volatile("cp.async.ca.shared.global [%0], [%1], 4, %2;" :: "r"(dst), "l"(src), "r"(sz));
}
#define CP_COMMIT() asm volatile("cp.async.commit_group;")
#define CP_WAIT1()  asm volatile("cp.async.wait_group 1;")
#define CP_WAIT0()  asm volatile("cp.async.wait_group 0;")

// ============================================================================
// Gate: logits = emb @ W + b ; top-32 (tie-break lower idx) ; softmax ; scatter
// ============================================================================
__global__ void gate_kernel(const float* __restrict__ emb,
                            const float* __restrict__ g1w, const float* __restrict__ g1b,
                            const float* __restrict__ g2w, const float* __restrict__ g2b,
                            float* __restrict__ out) {
    const int b    = blockIdx.x;
    const int gate = blockIdx.y;
    const int c    = threadIdx.x;
    const float* gw = (gate == 0) ? g1w : g2w;
    const float* gb = (gate == 0) ? g1b : g2b;

    __shared__ float s_emb[EDIM];
    __shared__ float s_log[COUT];
    __shared__ float s_exp[COUT];

    s_emb[c] = emb[b * EDIM + c];
    __syncthreads();

    float l = gb[c];
    #pragma unroll 8
    for (int e = 0; e < EDIM; e++) l += s_emb[e] * gw[e * COUT + c];
    s_log[c] = l;
    __syncthreads();

    int rank = 0;
    float m = -1e30f;
    for (int j = 0; j < COUT; j++) {
        float lj = s_log[j];
        if (lj > l || (lj == l && j < c)) rank++;
        if (lj > m) m = lj;
    }
    bool sel = (rank < TOPK);
    float ev = sel ? expf(l - m) : 0.0f;
    s_exp[c] = ev;
    __syncthreads();

    float s = 0.f;
    for (int j = 0; j < COUT; j++) s += s_exp[j];
    float gv = ev / s;

    out[OUT6_SIZE + gate * (BATCH * COUT) + b * COUT + c] = gv;

    if (gate == 0) {
        if (sel) { d_idx1[b * TOPK + rank] = c; d_gv1[b * TOPK + rank] = gv; }
    } else {
        d_slot2[b * COUT + c] = sel ? rank : -1;
        if (sel) { d_idx2[b * TOPK + rank] = c; d_gv2[b * TOPK + rank] = gv; }
    }
}

// ============================================================================
// conv1: 3x3 s2 p1, 32 gated channels, cp.async double-buffered pipeline.
// Tile 8x64 outputs, 256 thr, thread = 2 adjacent pixels, 32 packed acc.
// ============================================================================
#define C1_XSTR 132
__global__ void __launch_bounds__(256) conv1_kernel(const float* __restrict__ x,
                                                    const float* __restrict__ w1) {
    const int b = blockIdx.y, tile = blockIdx.x;
    const int h0 = (tile / 3) * 8, w0 = (tile % 3) * 64;
    const int tid = threadIdx.x;
    const int py = tid >> 5, px = tid & 31;

    __shared__ int   s_idx[TOPK];
    __shared__ float s_gv[TOPK];
    __shared__ __align__(16) float s_w[2][4 * TOPK * 20];   // 20.5 KB
    __shared__ __align__(16) float s_x[2][17 * C1_XSTR];    // 17.9 KB

    if (tid < TOPK) { s_idx[tid] = d_idx1[b * TOPK + tid]; s_gv[tid] = d_gv1[b * TOPK + tid]; }
    __syncthreads();

    u64 acc[TOPK];
    #pragma unroll
    for (int i = 0; i < TOPK; i++) acc[i] = 0ull;

    // ---- prologue: stage weights chunk0 + x plane0 ----
    {
        for (int i = tid; i < 4 * TOPK * 9; i += 256) {
            int ci_l = i / (TOPK * 9);
            int r = i - ci_l * (TOPK * 9);
            int co = r / 9, k = r - co * 9;
            const float* src = w1 + (s_idx[co] * CIN + ci_l) * 9 + k;
            unsigned dst = smem_u32(&s_w[0][(ci_l * TOPK + co) * 20 + 2 * k]);
            cp4(dst, src, 4); cp4(dst + 4, src, 4);
        }
        const float* sp = x + (size_t)(b * CIN + 0) * HIN * WIN;
        for (int i = tid; i < 17 * 129; i += 256) {
            int r = i / 129, cl = i - r * 129;
            int gr = 2 * h0 - 1 + r, gc = 2 * w0 - 1 + cl;
            int ok = (gr >= 0 && gr < HIN && gc >= 0 && gc < WIN) ? 4 : 0;
            cp4(smem_u32(&s_x[0][r * C1_XSTR + cl]), sp + gr * WIN + gc, ok);
        }
        CP_COMMIT();
    }

    for (int s = 0; s < CIN; s++) {
        if (s + 1 < CIN) {
            const int sn = s + 1;
            if ((sn & 3) == 0) {                      // next weight chunk
                const int chunk = sn >> 2, wb = chunk & 1;
                for (int i = tid; i < 4 * TOPK * 9; i += 256) {
                    int ci_l = i / (TOPK * 9);
                    int r = i - ci_l * (TOPK * 9);
                    int co = r / 9, k = r - co * 9;
                    const float* src = w1 + (s_idx[co] * CIN + chunk * 4 + ci_l) * 9 + k;
                    unsigned dst = smem_u32(&s_w[wb][(ci_l * TOPK + co) * 20 + 2 * k]);
                    cp4(dst, src, 4); cp4(dst + 4, src, 4);
                }
            }
            const float* sp = x + (size_t)(b * CIN + sn) * HIN * WIN;
            const int xb = sn & 1;
            for (int i = tid; i < 17 * 129; i += 256) {
                int r = i / 129, cl = i - r * 129;
                int gr = 2 * h0 - 1 + r, gc = 2 * w0 - 1 + cl;
                int ok = (gr >= 0 && gr < HIN && gc >= 0 && gc < WIN) ? 4 : 0;
                cp4(smem_u32(&s_x[xb][r * C1_XSTR + cl]), sp + gr * WIN + gc, ok);
            }
            CP_COMMIT();
            CP_WAIT1();
        } else {
            CP_WAIT0();
        }
        __syncthreads();

        // ---- compute plane s ----
        {
            const float* xp = &s_x[s & 1][(2 * py) * C1_XSTR + 4 * px];
            u64 p[9];
            #pragma unroll
            for (int r = 0; r < 3; r++) {
                float4 a = *(const float4*)(xp + r * C1_XSTR);
                float  e = xp[r * C1_XSTR + 4];
                p[r * 3 + 0] = pk2(a.x, a.z);
                p[r * 3 + 1] = pk2(a.y, a.w);
                p[r * 3 + 2] = pk2(a.z, e);
            }
            const float* wc = &s_w[(s >> 2) & 1][(s & 3) * TOPK * 20];
            #pragma unroll
            for (int co = 0; co < TOPK; co++) {
                const u64* wp = (const u64*)(wc + co * 20);
                ulonglong2 q0 = *(const ulonglong2*)(wp + 0);
                ulonglong2 q1 = *(const ulonglong2*)(wp + 2);
                ulonglong2 q2 = *(const ulonglong2*)(wp + 4);
                ulonglong2 q3 = *(const ulonglong2*)(wp + 6);
                u64        q4 = wp[8];
                fma2(acc[co], p[0], q0.x); fma2(acc[co], p[1], q0.y);
                fma2(acc[co], p[2], q1.x); fma2(acc[co], p[3], q1.y);
                fma2(acc[co], p[4], q2.x); fma2(acc[co], p[5], q2.y);
                fma2(acc[co], p[6], q3.x); fma2(acc[co], p[7], q3.y);
                fma2(acc[co], p[8], q4);
            }
        }
        __syncthreads();
    }

    const int h = h0 + py, w = w0 + 2 * px;
    #pragma unroll
    for (int co = 0; co < TOPK; co++) {
        float lo, hi; upk2(acc[co], lo, hi);
        float g = s_gv[co];
        float2 o;
        o.x = leaky(lo * g);
        o.y = leaky(hi * g);
        *(float2*)&d_out2p[((size_t)(b * TOPK + co) * P2H + h + 1) * P2W + (w + 2)] = o;
    }
}

// ============================================================================
// conv2: 3x3 s1 p1, 32 compact in -> 32 compact out, cp.async pipeline.
// Input read from zero-padded d_out2p (no bounds checks).
// ============================================================================
#define C2_XSTR 68
__global__ void __launch_bounds__(256) conv2_kernel(const float* __restrict__ w2) {
    const int b = blockIdx.y, tile = blockIdx.x;
    const int h0 = (tile / 3) * 8, w0 = (tile % 3) * 64;
    const int tid = threadIdx.x;
    const int py = tid >> 5, px = tid & 31;

    __shared__ int   s_idx1[TOPK];
    __shared__ int   s_idx2[TOPK];
    __shared__ float s_gv[TOPK];
    __shared__ __align__(16) float s_w[2][4 * TOPK * 20];   // 20.5 KB
    __shared__ __align__(16) float s_x[2][10 * C2_XSTR];    // 5.4 KB

    if (tid < TOPK) {
        s_idx1[tid] = d_idx1[b * TOPK + tid];
        s_idx2[tid] = d_idx2[b * TOPK + tid];
        s_gv[tid]   = d_gv2[b * TOPK + tid];
    }
    __syncthreads();

    u64 acc[TOPK];
    #pragma unroll
    for (int i = 0; i < TOPK; i++) acc[i] = 0ull;

    // prologue
    {
        for (int i = tid; i < 4 * TOPK * 9; i += 256) {
            int ci_l = i / (TOPK * 9);
            int r = i - ci_l * (TOPK * 9);
            int co = r / 9, k = r - co * 9;
            const float* src = w2 + (s_idx2[co] * COUT + s_idx1[ci_l]) * 9 + k;
            unsigned dst = smem_u32(&s_w[0][(ci_l * TOPK + co) * 20 + 2 * k]);
            cp4(dst, src, 4); cp4(dst + 4, src, 4);
        }
        const float* sp = d_out2p + (size_t)(b * TOPK + 0) * P2H * P2W;
        for (int i = tid; i < 10 * 66; i += 256) {
            int r = i / 66, cl = i - r * 66;
            cp4(smem_u32(&s_x[0][r * C2_XSTR + cl]), sp + (h0 + r) * P2W + (w0 + cl + 1), 4);
        }
        CP_COMMIT();
    }

    for (int s = 0; s < TOPK; s++) {
        if (s + 1 < TOPK) {
            const int sn = s + 1;
            if ((sn & 3) == 0) {
                const int chunk = sn >> 2, wb = chunk & 1;
                for (int i = tid; i < 4 * TOPK * 9; i += 256) {
                    int ci_l = i / (TOPK * 9);
                    int r = i - ci_l * (TOPK * 9);
                    int co = r / 9, k = r - co * 9;
                    const float* src = w2 + (s_idx2[co] * COUT + s_idx1[chunk * 4 + ci_l]) * 9 + k;
                    unsigned dst = smem_u32(&s_w[wb][(ci_l * TOPK + co) * 20 + 2 * k]);
                    cp4(dst, src, 4); cp4(dst + 4, src, 4);
                }
            }
            const float* sp = d_out2p + (size_t)(b * TOPK + sn) * P2H * P2W;
            const int xb = sn & 1;
            for (int i = tid; i < 10 * 66; i += 256) {
                int r = i / 66, cl = i - r * 66;
                cp4(smem_u32(&s_x[xb][r * C2_XSTR + cl]), sp + (h0 + r) * P2W + (w0 + cl + 1), 4);
            }
            CP_COMMIT();
            CP_WAIT1();
        } else {
            CP_WAIT0();
        }
        __syncthreads();

        {
            const float* xp = &s_x[s & 1][py * C2_XSTR + 2 * px];
            u64 p[9];
            #pragma unroll
            for (int r = 0; r < 3; r++) {
                float2 a = *(const float2*)(xp + r * C2_XSTR);
                float2 c = *(const float2*)(xp + r * C2_XSTR + 2);
                p[r * 3 + 0] = pk2(a.x, a.y);
                p[r * 3 + 1] = pk2(a.y, c.x);
                p[r * 3 + 2] = pk2(c.x, c.y);
            }
            const float* wc = &s_w[(s >> 2) & 1][(s & 3) * TOPK * 20];
            #pragma unroll
            for (int co = 0; co < TOPK; co++) {
                const u64* wp = (const u64*)(wc + co * 20);
                ulonglong2 q0 = *(const ulonglong2*)(wp + 0);
                ulonglong2 q1 = *(const ulonglong2*)(wp + 2);
                ulonglong2 q2 = *(const ulonglong2*)(wp + 4);
                ulonglong2 q3 = *(const ulonglong2*)(wp + 6);
                u64        q4 = wp[8];
                fma2(acc[co], p[0], q0.x); fma2(acc[co], p[1], q0.y);
                fma2(acc[co], p[2], q1.x); fma2(acc[co], p[3], q1.y);
                fma2(acc[co], p[4], q2.x); fma2(acc[co], p[5], q2.y);
                fma2(acc[co], p[6], q3.x); fma2(acc[co], p[7], q3.y);
                fma2(acc[co], p[8], q4);
            }
        }
        __syncthreads();
    }

    const int h = h0 + py, w = w0 + 2 * px;
    #pragma unroll
    for (int co = 0; co < TOPK; co++) {
        float lo, hi; upk2(acc[co], lo, hi);
        float g = s_gv[co];
        float2 o;
        o.x = leaky(lo * g);
        o.y = leaky(hi * g);
        *(float2*)&d_out4[((b * TOPK + co) * OH + h) * OW + w] = o;
    }
}

// ============================================================================
// ds: dense 1x1 s2 conv + BN(eval) + add sparse out4 + leaky -> out6.
// 16 channels per block (grid 36 x 8 x 8) for occupancy; packed f32x2.
// ============================================================================
#define DSG 16
__global__ void __launch_bounds__(256) ds_kernel(const float* __restrict__ x,
                                                 const float* __restrict__ dsw,
                                                 const float* __restrict__ gamma,
                                                 const float* __restrict__ beta,
                                                 float* __restrict__ out) {
    const int b    = blockIdx.z;
    const int cg   = blockIdx.y;                 // 8 groups of 16 channels
    const int tile = blockIdx.x;
    const int h0 = (tile / 3) * 8;
    const int w0 = (tile % 3) * 64;
    const int tid = threadIdx.x;
    const int py = tid >> 5, px = tid & 31;
    const int h = h0 + py, w = w0 + 2 * px;

    __shared__ __align__(16) float s_w[CIN * 2 * DSG];   // dup pairs: 8 KB
    __shared__ float s_scale[DSG];
    __shared__ float s_beta[DSG];
    __shared__ int   s_slot[DSG];

    for (int i = tid; i < CIN * DSG; i += 256) {
        int ci = i / DSG, co = i % DSG;
        float wv = dsw[(cg * DSG + co) * CIN + ci];
        float* dst = &s_w[ci * 2 * DSG + 2 * co];
        dst[0] = wv; dst[1] = wv;
    }
    if (tid < DSG) {
        int c = cg * DSG + tid;
        s_scale[tid] = gamma[c] * rsqrtf(1.0f + 1e-5f);
        s_beta[tid]  = beta[c];
        s_slot[tid]  = d_slot2[b * COUT + c];
    }
    __syncthreads();

    u64 acc[DSG];
    #pragma unroll
    for (int i = 0; i < DSG; i++) acc[i] = 0ull;

    const float* xb = x + ((size_t)b * CIN * HIN + 2 * h) * WIN + 2 * w;
    #pragma unroll 8
    for (int ci = 0; ci < CIN; ci++) {
        float4 xv = *(const float4*)(xb + (size_t)ci * HIN * WIN);
        u64 xp = pk2(xv.x, xv.z);
        const u64* wr = (const u64*)&s_w[ci * 2 * DSG];
        #pragma unroll
        for (int co = 0; co < DSG; co += 2) {
            ulonglong2 q = *(const ulonglong2*)(wr + co);
            fma2(acc[co],     xp, q.x);
            fma2(acc[co + 1], xp, q.y);
        }
    }

    #pragma unroll
    for (int co = 0; co < DSG; co++) {
        int c = cg * DSG + co;
        float lo, hi; upk2(acc[co], lo, hi);
        float sc = s_scale[co], be = s_beta[co];
        lo = lo * sc + be;
        hi = hi * sc + be;
        int slot = s_slot[co];
        if (slot >= 0) {
            float2 a = *(const float2*)&d_out4[((b * TOPK + slot) * OH + h) * OW + w];
            lo += a.x; hi += a.y;
        }
        float2 o;
        o.x = leaky(lo);
        o.y = leaky(hi);
        *(float2*)&out[((b * COUT + c) * OH + h) * OW + w] = o;
    }
}

// ============================================================================
extern "C" void kernel_launch(void* const* d_in, const int* in_sizes, int n_in,
                              void* d_out, int out_size) {
    const float* x     = (const float*)d_in[0];
    const float* emb   = (const float*)d_in[1];
    const float* w1    = (const float*)d_in[2];
    const float* w2    = (const float*)d_in[3];
    const float* dsw   = (const float*)d_in[4];
    const float* gam   = (const float*)d_in[5];
    const float* bet   = (const float*)d_in[6];
    const float* g1w   = (const float*)d_in[7];
    const float* g1b   = (const float*)d_in[8];
    const float* g2w   = (const float*)d_in[9];
    const float* g2b   = (const float*)d_in[10];
    float* out = (float*)d_out;

    gate_kernel<<<dim3(BATCH, 2), 128>>>(emb, g1w, g1b, g2w, g2b, out);
    conv1_kernel<<<dim3(36, BATCH), 256>>>(x, w1);
    conv2_kernel<<<dim3(36, BATCH), 256>>>(w2);
    ds_kernel<<<dim3(36, 8, BATCH), 256>>>(x, dsw, gam, bet, out);
}

// round 4
// speedup vs baseline: 1.1549x; 1.0338x over previous
#include <cuda_runtime.h>
#include <math.h>

#define BATCH 8
#define CIN   64
#define COUT  128
#define EDIM  128
#define HIN   192
#define WIN   384
#define OH    96
#define OW    192
#define TOPK  32
#define OUT6_SIZE (BATCH*COUT*OH*OW)

// padded conv2 input: rows 98 (1+96+1), col stride 196 (2+192+1+1)
#define P2H 98
#define P2W 196

typedef unsigned long long u64;

// ---- scratch (zero-initialized at module load; borders never written) ----
__device__ float d_out2p[BATCH*TOPK*P2H*P2W];  // padded leaky(conv1*g1)
__device__ int   d_idx1[BATCH*TOPK];
__device__ float d_gv1 [BATCH*TOPK];
__device__ int   d_idx2[BATCH*TOPK];
__device__ float d_gv2 [BATCH*TOPK];
__device__ int   d_slot2[BATCH*COUT];

__device__ __forceinline__ float leaky(float v) { return v >= 0.f ? v : 0.2f * v; }

__device__ __forceinline__ u64 pk2(float lo, float hi) {
    u64 r; asm("mov.b64 %0, {%1, %2};" : "=l"(r) : "f"(lo), "f"(hi)); return r;
}
__device__ __forceinline__ void upk2(u64 v, float& lo, float& hi) {
    asm("mov.b64 {%0, %1}, %2;" : "=f"(lo), "=f"(hi) : "l"(v));
}
__device__ __forceinline__ void fma2(u64& d, u64 a, u64 b) {
    asm("fma.rn.f32x2 %0, %1, %2, %0;" : "+l"(d) : "l"(a), "l"(b));
}
__device__ __forceinline__ unsigned smem_u32(const void* p) {
    return (unsigned)__cvta_generic_to_shared(p);
}
__device__ __forceinline__ void cp4(unsigned dst, const void* src, int sz) {
    asm volatile("cp.async.ca.shared.global [%0], [%1], 4, %2;" :: "r"(dst), "l"(src), "r"(sz));
}
#define CP_COMMIT() asm volatile("cp.async.commit_group;")
#define CP_WAIT1()  asm volatile("cp.async.wait_group 1;")
#define CP_WAIT0()  asm volatile("cp.async.wait_group 0;")

// ============================================================================
// Gate: logits = emb @ W + b ; top-32 (tie-break lower idx) ; softmax ; scatter
// ============================================================================
__global__ void gate_kernel(const float* __restrict__ emb,
                            const float* __restrict__ g1w, const float* __restrict__ g1b,
                            const float* __restrict__ g2w, const float* __restrict__ g2b,
                            float* __restrict__ out) {
    const int b    = blockIdx.x;
    const int gate = blockIdx.y;
    const int c    = threadIdx.x;
    const float* gw = (gate == 0) ? g1w : g2w;
    const float* gb = (gate == 0) ? g1b : g2b;

    __shared__ float s_emb[EDIM];
    __shared__ float s_log[COUT];
    __shared__ float s_exp[COUT];

    s_emb[c] = emb[b * EDIM + c];
    __syncthreads();

    float l = gb[c];
    #pragma unroll 8
    for (int e = 0; e < EDIM; e++) l += s_emb[e] * gw[e * COUT + c];
    s_log[c] = l;
    __syncthreads();

    int rank = 0;
    float m = -1e30f;
    for (int j = 0; j < COUT; j++) {
        float lj = s_log[j];
        if (lj > l || (lj == l && j < c)) rank++;
        if (lj > m) m = lj;
    }
    bool sel = (rank < TOPK);
    float ev = sel ? expf(l - m) : 0.0f;
    s_exp[c] = ev;
    __syncthreads();

    float s = 0.f;
    for (int j = 0; j < COUT; j++) s += s_exp[j];
    float gv = ev / s;

    out[OUT6_SIZE + gate * (BATCH * COUT) + b * COUT + c] = gv;

    if (gate == 0) {
        if (sel) { d_idx1[b * TOPK + rank] = c; d_gv1[b * TOPK + rank] = gv; }
    } else {
        d_slot2[b * COUT + c] = sel ? rank : -1;
        if (sel) { d_idx2[b * TOPK + rank] = c; d_gv2[b * TOPK + rank] = gv; }
    }
}

// ============================================================================
// ds_ident: dense 1x1 s2 conv + BN(eval). For gate2-selected channels writes
// RAW ident (conv2 fuses the add+leaky later); else writes leaky(ident).
// Thread: 16 co x 4 px. Block: 8 rows x 64 cols x 32 co. grid (36,4,BATCH).
// ============================================================================
__global__ void __launch_bounds__(256, 2) ds_kernel(const float* __restrict__ x,
                                                    const float* __restrict__ dsw,
                                                    const float* __restrict__ gamma,
                                                    const float* __restrict__ beta,
                                                    float* __restrict__ out) {
    const int b    = blockIdx.z;
    const int cgy  = blockIdx.y;                  // 4 groups of 32 channels
    const int tile = blockIdx.x;
    const int h0 = (tile / 3) * 8;
    const int w0 = (tile % 3) * 64;
    const int tid = threadIdx.x;
    const int cog = tid >> 7;                     // 0/1: 16-co half
    const int t   = tid & 127;
    const int row = t >> 4;                       // 0..7
    const int cq  = t & 15;                       // cols 4cq..4cq+3
    const int h = h0 + row, w = w0 + 4 * cq;

    __shared__ __align__(16) float s_w[CIN][64];  // [ci][co dup pairs]: 16 KB
    __shared__ float s_scale[32];
    __shared__ float s_beta[32];
    __shared__ int   s_slot[32];

    for (int i = tid; i < CIN * 32; i += 256) {
        int ci = i >> 5, co = i & 31;
        float wv = dsw[(cgy * 32 + co) * CIN + ci];
        s_w[ci][2 * co] = wv; s_w[ci][2 * co + 1] = wv;
    }
    if (tid < 32) {
        int c = cgy * 32 + tid;
        s_scale[tid] = gamma[c] * rsqrtf(1.0f + 1e-5f);
        s_beta[tid]  = beta[c];
        s_slot[tid]  = d_slot2[b * COUT + c];
    }
    __syncthreads();

    u64 acc[16][2];
    #pragma unroll
    for (int i = 0; i < 16; i++) { acc[i][0] = 0ull; acc[i][1] = 0ull; }

    const float* xb = x + ((size_t)b * CIN * HIN + 2 * h) * WIN + 2 * w;
    #pragma unroll 4
    for (int ci = 0; ci < CIN; ci++) {
        const float* p = xb + (size_t)ci * HIN * WIN;
        float4 A = *(const float4*)(p);
        float4 B = *(const float4*)(p + 4);
        u64 xa = pk2(A.x, A.z);
        u64 xc = pk2(B.x, B.z);
        const u64* wr = (const u64*)&s_w[ci][cog * 32];
        #pragma unroll
        for (int j = 0; j < 8; j++) {
            ulonglong2 q = *(const ulonglong2*)(wr + 2 * j);
            fma2(acc[2*j][0],   xa, q.x); fma2(acc[2*j][1],   xc, q.x);
            fma2(acc[2*j+1][0], xa, q.y); fma2(acc[2*j+1][1], xc, q.y);
        }
    }

    #pragma unroll
    for (int j = 0; j < 16; j++) {
        int co = cog * 16 + j;
        int c = cgy * 32 + co;
        float v0, v1, v2, v3;
        upk2(acc[j][0], v0, v1);
        upk2(acc[j][1], v2, v3);
        float sc = s_scale[co], be = s_beta[co];
        v0 = v0 * sc + be; v1 = v1 * sc + be; v2 = v2 * sc + be; v3 = v3 * sc + be;
        float4 o;
        if (s_slot[co] < 0) {
            o.x = leaky(v0); o.y = leaky(v1); o.z = leaky(v2); o.w = leaky(v3);
        } else {
            o.x = v0; o.y = v1; o.z = v2; o.w = v3;   // raw; conv2 finishes it
        }
        *(float4*)&out[((size_t)(b * COUT + c) * OH + h) * OW + w] = o;
    }
}

// ============================================================================
// conv1: 3x3 s2 p1, 32 gated channels, cp.async double-buffered pipeline.
// Thread: 16 co x 4 px. Block: 8 rows x 64 cols. grid (36, BATCH).
// ============================================================================
#define C1_XSTR 132
__global__ void __launch_bounds__(256, 2) conv1_kernel(const float* __restrict__ x,
                                                       const float* __restrict__ w1) {
    const int b = blockIdx.y, tile = blockIdx.x;
    const int h0 = (tile / 3) * 8, w0 = (tile % 3) * 64;
    const int tid = threadIdx.x;
    const int cog = tid >> 7;
    const int t   = tid & 127;
    const int row = t >> 4;
    const int cq  = t & 15;

    __shared__ int   s_idx[TOPK];
    __shared__ float s_gv[TOPK];
    __shared__ __align__(16) float s_w[2][4 * TOPK * 20];   // 20.5 KB
    __shared__ __align__(16) float s_x[2][17 * C1_XSTR];    // 17.9 KB

    if (tid < TOPK) { s_idx[tid] = d_idx1[b * TOPK + tid]; s_gv[tid] = d_gv1[b * TOPK + tid]; }
    __syncthreads();

    u64 acc[16][2];
    #pragma unroll
    for (int i = 0; i < 16; i++) { acc[i][0] = 0ull; acc[i][1] = 0ull; }

    // prologue: weights chunk0 + x plane0
    {
        for (int i = tid; i < 4 * TOPK * 9; i += 256) {
            int ci_l = i / (TOPK * 9);
            int r = i - ci_l * (TOPK * 9);
            int co = r / 9, k = r - co * 9;
            const float* src = w1 + (s_idx[co] * CIN + ci_l) * 9 + k;
            unsigned dst = smem_u32(&s_w[0][(ci_l * TOPK + co) * 20 + 2 * k]);
            cp4(dst, src, 4); cp4(dst + 4, src, 4);
        }
        const float* sp = x + (size_t)(b * CIN + 0) * HIN * WIN;
        for (int i = tid; i < 17 * 129; i += 256) {
            int r = i / 129, cl = i - r * 129;
            int gr = 2 * h0 - 1 + r, gc = 2 * w0 - 1 + cl;
            int ok = (gr >= 0 && gr < HIN && gc >= 0 && gc < WIN) ? 4 : 0;
            cp4(smem_u32(&s_x[0][r * C1_XSTR + cl]), sp + gr * WIN + gc, ok);
        }
        CP_COMMIT();
    }

    for (int s = 0; s < CIN; s++) {
        if (s + 1 < CIN) {
            const int sn = s + 1;
            if ((sn & 3) == 0) {
                const int chunk = sn >> 2, wb = chunk & 1;
                for (int i = tid; i < 4 * TOPK * 9; i += 256) {
                    int ci_l = i / (TOPK * 9);
                    int r = i - ci_l * (TOPK * 9);
                    int co = r / 9, k = r - co * 9;
                    const float* src = w1 + (s_idx[co] * CIN + chunk * 4 + ci_l) * 9 + k;
                    unsigned dst = smem_u32(&s_w[wb][(ci_l * TOPK + co) * 20 + 2 * k]);
                    cp4(dst, src, 4); cp4(dst + 4, src, 4);
                }
            }
            const float* sp = x + (size_t)(b * CIN + sn) * HIN * WIN;
            const int xb2 = sn & 1;
            for (int i = tid; i < 17 * 129; i += 256) {
                int r = i / 129, cl = i - r * 129;
                int gr = 2 * h0 - 1 + r, gc = 2 * w0 - 1 + cl;
                int ok = (gr >= 0 && gr < HIN && gc >= 0 && gc < WIN) ? 4 : 0;
                cp4(smem_u32(&s_x[xb2][r * C1_XSTR + cl]), sp + gr * WIN + gc, ok);
            }
            CP_COMMIT();
            CP_WAIT1();
        } else {
            CP_WAIT0();
        }
        __syncthreads();

        {
            const float* xp = &s_x[s & 1][(2 * row) * C1_XSTR + 8 * cq];
            u64 pa[9], pb[9];
            #pragma unroll
            for (int r = 0; r < 3; r++) {
                float4 A = *(const float4*)(xp + r * C1_XSTR);
                float4 B = *(const float4*)(xp + r * C1_XSTR + 4);
                float  e = xp[r * C1_XSTR + 8];
                pa[3*r+0] = pk2(A.x, A.z); pa[3*r+1] = pk2(A.y, A.w); pa[3*r+2] = pk2(A.z, B.x);
                pb[3*r+0] = pk2(B.x, B.z); pb[3*r+1] = pk2(B.y, B.w); pb[3*r+2] = pk2(B.z, e);
            }
            const float* wc = &s_w[(s >> 2) & 1][((s & 3) * TOPK + cog * 16) * 20];
            #pragma unroll
            for (int j = 0; j < 16; j++) {
                const u64* wp = (const u64*)(wc + j * 20);
                ulonglong2 q0 = *(const ulonglong2*)(wp + 0);
                ulonglong2 q1 = *(const ulonglong2*)(wp + 2);
                ulonglong2 q2 = *(const ulonglong2*)(wp + 4);
                ulonglong2 q3 = *(const ulonglong2*)(wp + 6);
                u64        q4 = wp[8];
                fma2(acc[j][0], pa[0], q0.x); fma2(acc[j][1], pb[0], q0.x);
                fma2(acc[j][0], pa[1], q0.y); fma2(acc[j][1], pb[1], q0.y);
                fma2(acc[j][0], pa[2], q1.x); fma2(acc[j][1], pb[2], q1.x);
                fma2(acc[j][0], pa[3], q1.y); fma2(acc[j][1], pb[3], q1.y);
                fma2(acc[j][0], pa[4], q2.x); fma2(acc[j][1], pb[4], q2.x);
                fma2(acc[j][0], pa[5], q2.y); fma2(acc[j][1], pb[5], q2.y);
                fma2(acc[j][0], pa[6], q3.x); fma2(acc[j][1], pb[6], q3.x);
                fma2(acc[j][0], pa[7], q3.y); fma2(acc[j][1], pb[7], q3.y);
                fma2(acc[j][0], pa[8], q4);   fma2(acc[j][1], pb[8], q4);
            }
        }
        __syncthreads();
    }

    const int h = h0 + row, w = w0 + 4 * cq;
    #pragma unroll
    for (int j = 0; j < 16; j++) {
        int co = cog * 16 + j;
        float g = s_gv[co];
        float v0, v1, v2, v3;
        upk2(acc[j][0], v0, v1);
        upk2(acc[j][1], v2, v3);
        float* base = &d_out2p[((size_t)(b * TOPK + co) * P2H + h + 1) * P2W + (w + 2)];
        float2 o0; o0.x = leaky(v0 * g); o0.y = leaky(v1 * g);
        float2 o1; o1.x = leaky(v2 * g); o1.y = leaky(v3 * g);
        *(float2*)base = o0;
        *(float2*)(base + 2) = o1;
    }
}

// ============================================================================
// conv2: 3x3 s1 p1, 32 compact in -> 32 gated out channels; fused epilogue:
// out = leaky(ident_raw + conv*g2). Thread: 16 co x 4 px. grid (36, BATCH).
// ============================================================================
#define C2_XSTR 68
__global__ void __launch_bounds__(256, 2) conv2_kernel(const float* __restrict__ w2,
                                                       float* __restrict__ out) {
    const int b = blockIdx.y, tile = blockIdx.x;
    const int h0 = (tile / 3) * 8, w0 = (tile % 3) * 64;
    const int tid = threadIdx.x;
    const int cog = tid >> 7;
    const int t   = tid & 127;
    const int row = t >> 4;
    const int cq  = t & 15;

    __shared__ int   s_idx1[TOPK];
    __shared__ int   s_idx2[TOPK];
    __shared__ float s_gv[TOPK];
    __shared__ __align__(16) float s_w[2][4 * TOPK * 20];   // 20.5 KB
    __shared__ __align__(16) float s_x[2][10 * C2_XSTR];    // 5.4 KB

    if (tid < TOPK) {
        s_idx1[tid] = d_idx1[b * TOPK + tid];
        s_idx2[tid] = d_idx2[b * TOPK + tid];
        s_gv[tid]   = d_gv2[b * TOPK + tid];
    }
    __syncthreads();

    u64 acc[16][2];
    #pragma unroll
    for (int i = 0; i < 16; i++) { acc[i][0] = 0ull; acc[i][1] = 0ull; }

    // prologue
    {
        for (int i = tid; i < 4 * TOPK * 9; i += 256) {
            int ci_l = i / (TOPK * 9);
            int r = i - ci_l * (TOPK * 9);
            int co = r / 9, k = r - co * 9;
            const float* src = w2 + (s_idx2[co] * COUT + s_idx1[ci_l]) * 9 + k;
            unsigned dst = smem_u32(&s_w[0][(ci_l * TOPK + co) * 20 + 2 * k]);
            cp4(dst, src, 4); cp4(dst + 4, src, 4);
        }
        const float* sp = d_out2p + (size_t)(b * TOPK + 0) * P2H * P2W;
        for (int i = tid; i < 10 * 66; i += 256) {
            int r = i / 66, cl = i - r * 66;
            cp4(smem_u32(&s_x[0][r * C2_XSTR + cl]), sp + (h0 + r) * P2W + (w0 + cl + 1), 4);
        }
        CP_COMMIT();
    }

    for (int s = 0; s < TOPK; s++) {
        if (s + 1 < TOPK) {
            const int sn = s + 1;
            if ((sn & 3) == 0) {
                const int chunk = sn >> 2, wb = chunk & 1;
                for (int i = tid; i < 4 * TOPK * 9; i += 256) {
                    int ci_l = i / (TOPK * 9);
                    int r = i - ci_l * (TOPK * 9);
                    int co = r / 9, k = r - co * 9;
                    const float* src = w2 + (s_idx2[co] * COUT + s_idx1[chunk * 4 + ci_l]) * 9 + k;
                    unsigned dst = smem_u32(&s_w[wb][(ci_l * TOPK + co) * 20 + 2 * k]);
                    cp4(dst, src, 4); cp4(dst + 4, src, 4);
                }
            }
            const float* sp = d_out2p + (size_t)(b * TOPK + sn) * P2H * P2W;
            const int xb2 = sn & 1;
            for (int i = tid; i < 10 * 66; i += 256) {
                int r = i / 66, cl = i - r * 66;
                cp4(smem_u32(&s_x[xb2][r * C2_XSTR + cl]), sp + (h0 + r) * P2W + (w0 + cl + 1), 4);
            }
            CP_COMMIT();
            CP_WAIT1();
        } else {
            CP_WAIT0();
        }
        __syncthreads();

        {
            const float* xp = &s_x[s & 1][row * C2_XSTR + 4 * cq];
            u64 pa[9], pb[9];
            #pragma unroll
            for (int r = 0; r < 3; r++) {
                float4 A = *(const float4*)(xp + r * C2_XSTR);
                float2 B = *(const float2*)(xp + r * C2_XSTR + 4);
                pa[3*r+0] = pk2(A.x, A.y); pa[3*r+1] = pk2(A.y, A.z); pa[3*r+2] = pk2(A.z, A.w);
                pb[3*r+0] = pk2(A.z, A.w); pb[3*r+1] = pk2(A.w, B.x); pb[3*r+2] = pk2(B.x, B.y);
            }
            const float* wc = &s_w[(s >> 2) & 1][((s & 3) * TOPK + cog * 16) * 20];
            #pragma unroll
            for (int j = 0; j < 16; j++) {
                const u64* wp = (const u64*)(wc + j * 20);
                ulonglong2 q0 = *(const ulonglong2*)(wp + 0);
                ulonglong2 q1 = *(const ulonglong2*)(wp + 2);
                ulonglong2 q2 = *(const ulonglong2*)(wp + 4);
                ulonglong2 q3 = *(const ulonglong2*)(wp + 6);
                u64        q4 = wp[8];
                fma2(acc[j][0], pa[0], q0.x); fma2(acc[j][1], pb[0], q0.x);
                fma2(acc[j][0], pa[1], q0.y); fma2(acc[j][1], pb[1], q0.y);
                fma2(acc[j][0], pa[2], q1.x); fma2(acc[j][1], pb[2], q1.x);
                fma2(acc[j][0], pa[3], q1.y); fma2(acc[j][1], pb[3], q1.y);
                fma2(acc[j][0], pa[4], q2.x); fma2(acc[j][1], pb[4], q2.x);
                fma2(acc[j][0], pa[5], q2.y); fma2(acc[j][1], pb[5], q2.y);
                fma2(acc[j][0], pa[6], q3.x); fma2(acc[j][1], pb[6], q3.x);
                fma2(acc[j][0], pa[7], q3.y); fma2(acc[j][1], pb[7], q3.y);
                fma2(acc[j][0], pa[8], q4);   fma2(acc[j][1], pb[8], q4);
            }
        }
        __syncthreads();
    }

    const int h = h0 + row, w = w0 + 4 * cq;
    #pragma unroll
    for (int j = 0; j < 16; j++) {
        int co = cog * 16 + j;
        float g = s_gv[co];
        int c = s_idx2[co];
        float v0, v1, v2, v3;
        upk2(acc[j][0], v0, v1);
        upk2(acc[j][1], v2, v3);
        float* base = &out[((size_t)(b * COUT + c) * OH + h) * OW + w];
        float4 id = *(const float4*)base;
        float4 o;
        o.x = leaky(id.x + v0 * g);
        o.y = leaky(id.y + v1 * g);
        o.z = leaky(id.z + v2 * g);
        o.w = leaky(id.w + v3 * g);
        *(float4*)base = o;
    }
}

// ============================================================================
extern "C" void kernel_launch(void* const* d_in, const int* in_sizes, int n_in,
                              void* d_out, int out_size) {
    const float* x     = (const float*)d_in[0];
    const float* emb   = (const float*)d_in[1];
    const float* w1    = (const float*)d_in[2];
    const float* w2    = (const float*)d_in[3];
    const float* dsw   = (const float*)d_in[4];
    const float* gam   = (const float*)d_in[5];
    const float* bet   = (const float*)d_in[6];
    const float* g1w   = (const float*)d_in[7];
    const float* g1b   = (const float*)d_in[8];
    const float* g2w   = (const float*)d_in[9];
    const float* g2b   = (const float*)d_in[10];
    float* out = (float*)d_out;

    gate_kernel<<<dim3(BATCH, 2), 128>>>(emb, g1w, g1b, g2w, g2b, out);
    ds_kernel<<<dim3(36, 4, BATCH), 256>>>(x, dsw, gam, bet, out);
    conv1_kernel<<<dim3(36, BATCH), 256>>>(x, w1);
    conv2_kernel<<<dim3(36, BATCH), 256>>>(w2, out);
}